// round 1
// baseline (speedup 1.0000x reference)
#include <cuda_runtime.h>
#include <cstdint>
#include <cstddef>

#define B 256
#define L 2048
#define H 128
#define V 32000
#define BL (B * L)
#define TOK 128   // tokens per encode block

// Scratch (no cudaMalloc allowed): device globals.
__device__ float g_h[(size_t)BL * H];   // 256 MB: encoded h_all [B,L,H]
__device__ float g_r[B * H];            // r = M_fin @ h_last
__device__ float g_rp[B * H];           // rp = r @ Wrp + brp

// ---------------------------------------------------------------------------
// Encode: h_all = LN(e + relu(e@W1+b1)@W2 + b2) * gamma + beta
// Block = 256 threads, 128 tokens. SMEM: e[128][128] (64KB) + h1[128][256] (128KB).
// ---------------------------------------------------------------------------
__global__ void __launch_bounds__(256, 1) encode_kernel(
    const int* __restrict__ seq, const float* __restrict__ embed,
    const float* __restrict__ W1, const float* __restrict__ b1,
    const float* __restrict__ W2, const float* __restrict__ b2,
    const float* __restrict__ gamma, const float* __restrict__ beta)
{
    extern __shared__ float sm[];
    float* e_sm  = sm;             // [TOK][H]
    float* h1_sm = sm + TOK * H;   // [TOK][2H]
    __shared__ int toks[TOK];

    const int t = threadIdx.x;
    const int tile0 = blockIdx.x * TOK;

    if (t < TOK) toks[t] = seq[tile0 + t];
    __syncthreads();

    // Gather embeddings: coalesced over the H dimension.
    #pragma unroll
    for (int i = 0; i < (TOK * H) / 256; i++) {
        int idx = i * 256 + t;
        int m = idx >> 7;
        int k = idx & (H - 1);
        e_sm[idx] = embed[(size_t)toks[m] * H + k];
    }
    __syncthreads();

    const int tx = t & 31;       // lane
    const int ty = t >> 5;       // warp 0..7
    const int m0 = ty * 16;      // 16 tokens per warp

    // ---------------- GEMM1: h1 = relu(e @ W1 + b1), N=256, K=128 ----------
    {
        const int n0 = tx * 8;
        float acc[16][8];
        #pragma unroll
        for (int i = 0; i < 16; i++)
            #pragma unroll
            for (int j = 0; j < 8; j++) acc[i][j] = 0.f;

        #pragma unroll 2
        for (int k = 0; k < H; k++) {
            float4 w0 = *(const float4*)(W1 + (size_t)k * 256 + n0);
            float4 w1 = *(const float4*)(W1 + (size_t)k * 256 + n0 + 4);
            #pragma unroll
            for (int i = 0; i < 16; i++) {
                float ev = e_sm[(m0 + i) * H + k];   // broadcast LDS
                acc[i][0] += ev * w0.x; acc[i][1] += ev * w0.y;
                acc[i][2] += ev * w0.z; acc[i][3] += ev * w0.w;
                acc[i][4] += ev * w1.x; acc[i][5] += ev * w1.y;
                acc[i][6] += ev * w1.z; acc[i][7] += ev * w1.w;
            }
        }
        float4 bb0 = *(const float4*)(b1 + n0);
        float4 bb1 = *(const float4*)(b1 + n0 + 4);
        #pragma unroll
        for (int i = 0; i < 16; i++) {
            float4 r0, r1;
            r0.x = fmaxf(acc[i][0] + bb0.x, 0.f);
            r0.y = fmaxf(acc[i][1] + bb0.y, 0.f);
            r0.z = fmaxf(acc[i][2] + bb0.z, 0.f);
            r0.w = fmaxf(acc[i][3] + bb0.w, 0.f);
            r1.x = fmaxf(acc[i][4] + bb1.x, 0.f);
            r1.y = fmaxf(acc[i][5] + bb1.y, 0.f);
            r1.z = fmaxf(acc[i][6] + bb1.z, 0.f);
            r1.w = fmaxf(acc[i][7] + bb1.w, 0.f);
            *(float4*)(h1_sm + (m0 + i) * 256 + n0)     = r0;
            *(float4*)(h1_sm + (m0 + i) * 256 + n0 + 4) = r1;
        }
    }
    __syncthreads();

    // ---------------- GEMM2: ff = h1 @ W2 + b2, N=128, K=256 ---------------
    const int c0 = tx * 4;
    float acc2[16][4];
    #pragma unroll
    for (int i = 0; i < 16; i++)
        #pragma unroll
        for (int j = 0; j < 4; j++) acc2[i][j] = 0.f;

    #pragma unroll 2
    for (int k = 0; k < 2 * H; k++) {
        float4 w = *(const float4*)(W2 + (size_t)k * H + c0);
        #pragma unroll
        for (int i = 0; i < 16; i++) {
            float hv = h1_sm[(m0 + i) * 256 + k];   // broadcast LDS
            acc2[i][0] += hv * w.x; acc2[i][1] += hv * w.y;
            acc2[i][2] += hv * w.z; acc2[i][3] += hv * w.w;
        }
    }

    // ---------------- residual + LayerNorm + write --------------------------
    const float4 gv  = *(const float4*)(gamma + c0);
    const float4 bv  = *(const float4*)(beta + c0);
    const float4 b2v = *(const float4*)(b2 + c0);
    #pragma unroll
    for (int i = 0; i < 16; i++) {
        int m = m0 + i;
        const float4 ev = *(const float4*)(e_sm + m * H + c0);
        float y0 = acc2[i][0] + b2v.x + ev.x;
        float y1 = acc2[i][1] + b2v.y + ev.y;
        float y2 = acc2[i][2] + b2v.z + ev.z;
        float y3 = acc2[i][3] + b2v.w + ev.w;
        float s = (y0 + y1) + (y2 + y3);
        float q = y0 * y0 + y1 * y1 + y2 * y2 + y3 * y3;
        #pragma unroll
        for (int o = 16; o; o >>= 1) {
            s += __shfl_xor_sync(0xffffffffu, s, o);
            q += __shfl_xor_sync(0xffffffffu, q, o);
        }
        float mu  = s * (1.0f / H);
        float var = q * (1.0f / H) - mu * mu;
        float inv = rsqrtf(var + 1e-5f);
        float4 o4;
        o4.x = (y0 - mu) * inv * gv.x + bv.x;
        o4.y = (y1 - mu) * inv * gv.y + bv.y;
        o4.z = (y2 - mu) * inv * gv.z + bv.z;
        o4.w = (y3 - mu) * inv * gv.w + bv.w;
        *(float4*)(g_h + (size_t)(tile0 + m) * H + c0) = o4;
    }
}

// ---------------------------------------------------------------------------
// Scan: one CTA per batch. Thread i owns M row i (float4[32] in registers).
// 2047 sequential delta-rule steps; epilogue computes r = M @ h_last.
// ---------------------------------------------------------------------------
__global__ void __launch_bounds__(128, 2) scan_kernel()
{
    const int b = blockIdx.x;
    const int tid = threadIdx.x;
    const int lane = tid & 31;
    const int wid = tid >> 5;

    __shared__ float ks[2][H];
    __shared__ float red_kk[4];
    __shared__ float red_ee[4];

    float4 Mr[32];
    #pragma unroll
    for (int q = 0; q < 32; q++) Mr[q] = make_float4(0.f, 0.f, 0.f, 0.f);

    const float* hb = g_h + (size_t)b * L * H;
    float kv_next = hb[tid];   // k_0

    for (int t = 0; t < L - 1; t++) {
        const int buf = t & 1;
        const float kv = kv_next;
        ks[buf][tid] = kv;

        // kk = ||k||^2 (block reduce)
        float p = kv * kv;
        #pragma unroll
        for (int o = 16; o; o >>= 1) p += __shfl_xor_sync(0xffffffffu, p, o);
        if (lane == 0) red_kk[wid] = p;
        __syncthreads();                                   // BAR1

        kv_next = hb[(size_t)(t + 1) * H + tid];           // prefetch (t=2046 -> h_last)
        const float kk = (red_kk[0] + red_kk[1]) + (red_kk[2] + red_kk[3]);

        // vp_i = M_i . k
        const float4* k4 = (const float4*)ks[buf];
        float a0 = 0.f, a1 = 0.f, a2 = 0.f, a3 = 0.f;
        #pragma unroll
        for (int q = 0; q < 32; q++) {
            float4 kq = k4[q];
            a0 += Mr[q].x * kq.x; a1 += Mr[q].y * kq.y;
            a2 += Mr[q].z * kq.z; a3 += Mr[q].w * kq.w;
        }
        const float vp = (a0 + a1) + (a2 + a3);
        const float err = kv - vp / (kk + 1e-6f);

        // ee = ||err||^2 (block reduce)
        float pe = err * err;
        #pragma unroll
        for (int o = 16; o; o >>= 1) pe += __shfl_xor_sync(0xffffffffu, pe, o);
        if (lane == 0) red_ee[wid] = pe;
        __syncthreads();                                   // BAR2
        const float ee = (red_ee[0] + red_ee[1]) + (red_ee[2] + red_ee[3]);

        // gate = ||err|| > 0.4*||v||   (v = k  =>  compare squares)
        if (ee > 0.16f * kk) {                              // uniform branch
            #pragma unroll
            for (int q = 0; q < 32; q++) {
                float4 kq = k4[q];
                Mr[q].x += err * kq.x; Mr[q].y += err * kq.y;
                Mr[q].z += err * kq.z; Mr[q].w += err * kq.w;
            }
        }
    }

    // Epilogue: r_i = M_i . h_last  (kv_next holds h_last[tid])
    ks[1][tid] = kv_next;
    __syncthreads();
    const float4* k4 = (const float4*)ks[1];
    float a0 = 0.f, a1 = 0.f, a2 = 0.f, a3 = 0.f;
    #pragma unroll
    for (int q = 0; q < 32; q++) {
        float4 kq = k4[q];
        a0 += Mr[q].x * kq.x; a1 += Mr[q].y * kq.y;
        a2 += Mr[q].z * kq.z; a3 += Mr[q].w * kq.w;
    }
    g_r[b * H + tid] = (a0 + a1) + (a2 + a3);
}

// ---------------------------------------------------------------------------
// rp = r @ Wrp + brp   (tiny: 256 blocks x 128 threads)
// ---------------------------------------------------------------------------
__global__ void rp_kernel(const float* __restrict__ Wrp, const float* __restrict__ brp)
{
    const int b = blockIdx.x;
    const int i = threadIdx.x;
    __shared__ float rb[H];
    rb[i] = g_r[b * H + i];
    __syncthreads();
    float acc = brp[i];
    #pragma unroll 8
    for (int j = 0; j < H; j++) acc += rb[j] * Wrp[j * H + i];
    g_rp[b * H + i] = acc;
}

// ---------------------------------------------------------------------------
// out = rp @ Wout + bout.  Block: 256 thr, tile 64 batches x 128 vocab.
// ---------------------------------------------------------------------------
__global__ void __launch_bounds__(256) out_kernel(
    const float* __restrict__ Wout, const float* __restrict__ bout,
    float* __restrict__ out)
{
    __shared__ float rp_sm[64 * H];   // 32 KB
    const int t = threadIdx.x;
    const int v0 = blockIdx.x * 128;
    const int b0 = blockIdx.y * 64;

    #pragma unroll
    for (int i = 0; i < 32; i++) {
        int idx = i * 256 + t;
        rp_sm[idx] = g_rp[b0 * H + idx];
    }
    __syncthreads();

    const int tx = t & 31;
    const int ty = t >> 5;
    const int m0 = ty * 8;
    const int n  = v0 + tx * 4;

    float4 acc[8];
    #pragma unroll
    for (int i = 0; i < 8; i++) acc[i] = make_float4(0.f, 0.f, 0.f, 0.f);

    #pragma unroll 2
    for (int k = 0; k < H; k++) {
        float4 w = *(const float4*)(Wout + (size_t)k * V + n);
        #pragma unroll
        for (int i = 0; i < 8; i++) {
            float hv = rp_sm[(m0 + i) * H + k];   // broadcast LDS
            acc[i].x += hv * w.x; acc[i].y += hv * w.y;
            acc[i].z += hv * w.z; acc[i].w += hv * w.w;
        }
    }
    const float4 bo = *(const float4*)(bout + n);
    #pragma unroll
    for (int i = 0; i < 8; i++) {
        float4 o;
        o.x = acc[i].x + bo.x; o.y = acc[i].y + bo.y;
        o.z = acc[i].z + bo.z; o.w = acc[i].w + bo.w;
        *(float4*)(out + (size_t)(b0 + m0 + i) * V + n) = o;
    }
}

// ---------------------------------------------------------------------------
extern "C" void kernel_launch(void* const* d_in, const int* in_sizes, int n_in,
                              void* d_out, int out_size)
{
    const int*   seq   = (const int*)  d_in[0];
    const float* embed = (const float*)d_in[1];
    const float* W1    = (const float*)d_in[2];
    const float* b1    = (const float*)d_in[3];
    const float* W2    = (const float*)d_in[4];
    const float* b2    = (const float*)d_in[5];
    const float* gamma = (const float*)d_in[6];
    const float* beta  = (const float*)d_in[7];
    const float* Wrp   = (const float*)d_in[8];
    const float* brp   = (const float*)d_in[9];
    const float* Wout  = (const float*)d_in[10];
    const float* bout  = (const float*)d_in[11];
    float* out = (float*)d_out;

    const size_t enc_smem = (size_t)(TOK * H + TOK * 2 * H) * sizeof(float); // 196608
    cudaFuncSetAttribute(encode_kernel,
                         cudaFuncAttributeMaxDynamicSharedMemorySize,
                         (int)enc_smem);

    encode_kernel<<<BL / TOK, 256, enc_smem>>>(seq, embed, W1, b1, W2, b2, gamma, beta);
    scan_kernel<<<B, 128>>>();
    rp_kernel<<<B, H>>>(Wrp, brp);
    dim3 og(V / 128, B / 64);
    out_kernel<<<og, 256>>>(Wout, bout, out);
}